// round 9
// baseline (speedup 1.0000x reference)
#include <cuda_runtime.h>

#define N_NODES 50000
#define N_EDGES 1600000
#define F_IN    1433
#define HID     256
#define N_CLS   7

// ---------------- scratch (static device globals; no allocs allowed) ----------------
__device__ float g_h1[N_NODES * HID];        // X @ W1
__device__ float g_z1[N_NODES * HID];        // relu(Agg(h1)+b1)
__device__ float g_h2[N_NODES * N_CLS];      // z1 @ W2
__device__ float g_dinv[N_NODES];
__device__ int   g_cnt[N_NODES];
__device__ int   g_cursor[N_NODES];
__device__ int   g_rowptr[N_NODES + 1];
__device__ int   g_col[N_EDGES];
__device__ float g_w[N_EDGES];               // dinv[src] per CSR entry

// ---------------- packed f32x2 helpers (full-rate fp32 FMA pipe) ----------------
__device__ __forceinline__ unsigned long long pack2(float x, float y) {
    unsigned long long r;
    asm("mov.b64 %0, {%1, %2};" : "=l"(r) : "f"(x), "f"(y));
    return r;
}
__device__ __forceinline__ void unpack2(unsigned long long v, float& x, float& y) {
    asm("mov.b64 {%0, %1}, %2;" : "=f"(x), "=f"(y) : "l"(v));
}
__device__ __forceinline__ unsigned long long fma2(unsigned long long a,
                                                   unsigned long long b,
                                                   unsigned long long c) {
    unsigned long long d;
    asm("fma.rn.f32x2 %0, %1, %2, %3;" : "=l"(d) : "l"(a), "l"(b), "l"(c));
    return d;
}

// ---------------- graph preprocessing ----------------
__global__ void zero_cnt_kernel() {
    int i = blockIdx.x * blockDim.x + threadIdx.x;
    if (i < N_NODES) g_cnt[i] = 0;
}

// edge_index is INT32: jnp.int64 silently demotes to int32 (JAX x64 disabled)
__global__ void count_kernel(const int* __restrict__ ei) {
    int e = blockIdx.x * blockDim.x + threadIdx.x;
    if (e < N_EDGES) {
        int dst = ei[N_EDGES + e];
        if (dst >= 0 && dst < N_NODES) atomicAdd(&g_cnt[dst], 1);
    }
}

__global__ void dinv_kernel() {
    int i = blockIdx.x * blockDim.x + threadIdx.x;
    if (i < N_NODES) g_dinv[i] = rsqrtf((float)(g_cnt[i] + 1)); // +1 self-loop
}

// single-block exclusive scan over g_cnt -> g_rowptr (and cursor copy)
__global__ void scan_kernel() {
    __shared__ int sums[1024];
    const int CH = (N_NODES + 1023) / 1024;  // 49
    int t = threadIdx.x;
    int start = t * CH;
    int s = 0;
    for (int i = 0; i < CH; i++) {
        int idx = start + i;
        if (idx < N_NODES) s += g_cnt[idx];
    }
    sums[t] = s;
    __syncthreads();
    for (int off = 1; off < 1024; off <<= 1) {
        int v = 0;
        if (t >= off) v = sums[t - off];
        __syncthreads();
        if (t >= off) sums[t] += v;
        __syncthreads();
    }
    int run = (t == 0) ? 0 : sums[t - 1];
    for (int i = 0; i < CH; i++) {
        int idx = start + i;
        if (idx < N_NODES) {
            g_rowptr[idx] = run;
            g_cursor[idx] = run;
            run += g_cnt[idx];
        }
    }
    if (t == 1023) g_rowptr[N_NODES] = sums[1023];
}

__global__ void fill_kernel(const int* __restrict__ ei) {
    int e = blockIdx.x * blockDim.x + threadIdx.x;
    if (e < N_EDGES) {
        int src = ei[e];
        int dst = ei[N_EDGES + e];
        if (src < 0 || src >= N_NODES || dst < 0 || dst >= N_NODES) return;
        int pos = atomicAdd(&g_cursor[dst], 1);
        g_col[pos] = src;
        g_w[pos]   = g_dinv[src];
    }
}

// ---------------- GEMM1: h1 = X[50000,1433] @ W1[1433,256] ----------------
// 128x64 tile, 256 threads, 8x4 per thread, f32x2-packed accumulation.
#define BM 128
#define BN 64
#define BK 16

__global__ __launch_bounds__(256) void gemm1_kernel(const float* __restrict__ X,
                                                    const float* __restrict__ W1) {
    __shared__ __align__(16) float As[BK][BM + 4];  // row = 132 floats (528B)
    __shared__ __align__(16) float Bs[BK][BN + 4];  // row = 68 floats (272B)

    int t = threadIdx.x;
    int tr = t & 15;   // 16 row groups of 8
    int tc = t >> 4;   // 16 col groups of 4
    int row0 = blockIdx.x * BM;
    int col0 = blockIdx.y * BN;

    // acc2[p][j]: rows (tr*8+2p, tr*8+2p+1), col (tc*4+j), packed f32x2
    unsigned long long acc2[4][4];
#pragma unroll
    for (int p = 0; p < 4; p++)
#pragma unroll
        for (int j = 0; j < 4; j++) acc2[p][j] = 0ull;

    for (int k0 = 0; k0 < F_IN; k0 += BK) {
        // load A tile: 2048 elems, 8 per thread (16 consecutive k per row)
#pragma unroll
        for (int i = 0; i < 8; i++) {
            int idx = t + i * 256;
            int kk = idx & 15;
            int r  = idx >> 4;
            int gr = row0 + r;
            int gk = k0 + kk;
            As[kk][r] = (gr < N_NODES && gk < F_IN) ? X[(size_t)gr * F_IN + gk] : 0.0f;
        }
        // load B tile: 1024 elems, 4 per thread (64 consecutive cols per row)
#pragma unroll
        for (int i = 0; i < 4; i++) {
            int idx = t + i * 256;
            int c  = idx & 63;
            int kk = idx >> 6;
            int gk = k0 + kk;
            Bs[kk][c] = (gk < F_IN) ? W1[gk * HID + col0 + c] : 0.0f;
        }
        __syncthreads();

#pragma unroll
        for (int kk = 0; kk < BK; kk++) {
            const ulonglong2 a01 = *(const ulonglong2*)&As[kk][tr * 8];
            const ulonglong2 a23 = *(const ulonglong2*)&As[kk][tr * 8 + 4];
            unsigned long long ap[4] = {a01.x, a01.y, a23.x, a23.y};
            const float4 bv = *(const float4*)&Bs[kk][tc * 4];
            unsigned long long bb[4] = {pack2(bv.x, bv.x), pack2(bv.y, bv.y),
                                        pack2(bv.z, bv.z), pack2(bv.w, bv.w)};
#pragma unroll
            for (int p = 0; p < 4; p++)
#pragma unroll
                for (int j = 0; j < 4; j++)
                    acc2[p][j] = fma2(ap[p], bb[j], acc2[p][j]);
        }
        __syncthreads();
    }

    // store
#pragma unroll
    for (int p = 0; p < 4; p++) {
        float lo[4], hi[4];
#pragma unroll
        for (int j = 0; j < 4; j++) unpack2(acc2[p][j], lo[j], hi[j]);
        int gr0 = row0 + tr * 8 + 2 * p;
        int gc  = col0 + tc * 4;
        if (gr0 < N_NODES) {
#pragma unroll
            for (int j = 0; j < 4; j++) g_h1[(size_t)gr0 * HID + gc + j] = lo[j];
        }
        if (gr0 + 1 < N_NODES) {
#pragma unroll
            for (int j = 0; j < 4; j++) g_h1[(size_t)(gr0 + 1) * HID + gc + j] = hi[j];
        }
    }
}

// ---------------- Aggregation layer 1: z1 = relu(D^-1/2 A D^-1/2 h1 + b1) ----------------
// one block (64 threads) per dst node; each thread owns 4 contiguous cols (float4)
__global__ __launch_bounds__(64) void agg1_kernel(const float* __restrict__ b1) {
    __shared__ __align__(16) uint2 spair[64];  // {src, bits(w)}
    int u = blockIdx.x;
    int t = threadIdx.x;
    int start = g_rowptr[u];
    int end   = g_rowptr[u + 1];

    float4 acc = make_float4(0.f, 0.f, 0.f, 0.f);
    for (int base = start; base < end; base += 64) {
        int j = base + t;
        if (j < end) {
            spair[t] = make_uint2((unsigned)g_col[j], __float_as_uint(g_w[j]));
        }
        __syncthreads();
        int m = min(64, end - base);
#pragma unroll 4
        for (int q = 0; q < m; q++) {
            uint2 p = spair[q];
            const float4 hv = *(const float4*)&g_h1[(size_t)p.x * HID + t * 4];
            float w = __uint_as_float(p.y);
            acc.x = fmaf(hv.x, w, acc.x);
            acc.y = fmaf(hv.y, w, acc.y);
            acc.z = fmaf(hv.z, w, acc.z);
            acc.w = fmaf(hv.w, w, acc.w);
        }
        __syncthreads();
    }

    float di = g_dinv[u];
    float self = di * di;
    const float4 hs = *(const float4*)&g_h1[(size_t)u * HID + t * 4];
    const float4 bv = *(const float4*)&b1[t * 4];
    float4 o;
    o.x = fmaxf(di * acc.x + self * hs.x + bv.x, 0.f);
    o.y = fmaxf(di * acc.y + self * hs.y + bv.y, 0.f);
    o.z = fmaxf(di * acc.z + self * hs.z + bv.z, 0.f);
    o.w = fmaxf(di * acc.w + self * hs.w + bv.w, 0.f);
    *(float4*)&g_z1[(size_t)u * HID + t * 4] = o;
}

// ---------------- GEMM2: h2 = z1[50000,256] @ W2[256,7] ----------------
// one warp per node; 8 warps / block
__global__ __launch_bounds__(256) void gemm2_kernel(const float* __restrict__ W2) {
    __shared__ float w2s[HID * N_CLS];  // 1792 floats
    int t = threadIdx.x;
    for (int i = t; i < HID * N_CLS; i += 256) w2s[i] = W2[i];
    __syncthreads();

    int warp = t >> 5, lane = t & 31;
    int node = blockIdx.x * 8 + warp;
    if (node >= N_NODES) return;

    float acc[N_CLS];
#pragma unroll
    for (int c = 0; c < N_CLS; c++) acc[c] = 0.f;

#pragma unroll
    for (int kk = 0; kk < 8; kk++) {
        int k = lane + kk * 32;
        float v = g_z1[(size_t)node * HID + k];
#pragma unroll
        for (int c = 0; c < N_CLS; c++) acc[c] = fmaf(v, w2s[k * N_CLS + c], acc[c]);
    }
#pragma unroll
    for (int off = 16; off > 0; off >>= 1) {
#pragma unroll
        for (int c = 0; c < N_CLS; c++)
            acc[c] += __shfl_down_sync(0xffffffffu, acc[c], off);
    }
    if (lane == 0) {
#pragma unroll
        for (int c = 0; c < N_CLS; c++) g_h2[node * N_CLS + c] = acc[c];
    }
}

// ---------------- Aggregation layer 2 -> d_out ----------------
// one warp (block of 32) per dst node; lanes 0..6 own the 7 output cols
__global__ __launch_bounds__(32) void agg2_kernel(const float* __restrict__ b2,
                                                  float* __restrict__ out) {
    __shared__ uint2 spair[32];
    int u = blockIdx.x;
    int t = threadIdx.x;
    int start = g_rowptr[u];
    int end   = g_rowptr[u + 1];

    float acc = 0.f;
    for (int base = start; base < end; base += 32) {
        int j = base + t;
        if (j < end) {
            spair[t] = make_uint2((unsigned)g_col[j], __float_as_uint(g_w[j]));
        }
        __syncwarp();
        int m = min(32, end - base);
        if (t < N_CLS) {
            for (int q = 0; q < m; q++) {
                uint2 p = spair[q];
                acc = fmaf(g_h2[(size_t)p.x * N_CLS + t], __uint_as_float(p.y), acc);
            }
        }
        __syncwarp();
    }
    if (t < N_CLS) {
        float di = g_dinv[u];
        out[u * N_CLS + t] = di * acc + di * di * g_h2[(size_t)u * N_CLS + t] + b2[t];
    }
}

// ---------------- launch ----------------
extern "C" void kernel_launch(void* const* d_in, const int* in_sizes, int n_in,
                              void* d_out, int out_size) {
    const float* x   = (const float*)d_in[0];
    const int*   ei  = (const int*)d_in[1];   // int32! (JAX x64 disabled)
    const float* W1  = (const float*)d_in[2];
    const float* b1  = (const float*)d_in[3];
    const float* W2  = (const float*)d_in[4];
    const float* b2  = (const float*)d_in[5];
    float* out = (float*)d_out;

    // graph preprocessing (shared by both layers)
    zero_cnt_kernel<<<(N_NODES + 255) / 256, 256>>>();
    count_kernel<<<(N_EDGES + 255) / 256, 256>>>(ei);
    dinv_kernel<<<(N_NODES + 255) / 256, 256>>>();
    scan_kernel<<<1, 1024>>>();
    fill_kernel<<<(N_EDGES + 255) / 256, 256>>>(ei);

    // layer 1
    dim3 g1((N_NODES + BM - 1) / BM, HID / BN);
    gemm1_kernel<<<g1, 256>>>(x, W1);
    agg1_kernel<<<N_NODES, 64>>>(b1);

    // layer 2
    gemm2_kernel<<<(N_NODES + 7) / 8, 256>>>(W2);
    agg2_kernel<<<N_NODES, 32>>>(b2, out);
}

// round 10
// speedup vs baseline: 1.0018x; 1.0018x over previous
#include <cuda_runtime.h>

#define N_NODES 50000
#define N_EDGES 1600000
#define F_IN    1433
#define HID     256
#define N_CLS   7

// ---------------- scratch (static device globals; no allocs allowed) ----------------
__device__ float g_h1[N_NODES * HID];        // X @ W1
__device__ float g_z1[N_NODES * HID];        // relu(Agg(h1)+b1)
__device__ float g_h2[N_NODES * N_CLS];      // z1 @ W2
__device__ float g_dinv[N_NODES];
__device__ int   g_cnt[N_NODES];
__device__ int   g_cursor[N_NODES];
__device__ int   g_rowptr[N_NODES + 1];
__device__ int   g_col[N_EDGES];
__device__ float g_w[N_EDGES];               // dinv[src] per CSR entry

// ---------------- packed f32x2 helpers (full-rate fp32 FMA pipe) ----------------
__device__ __forceinline__ unsigned long long pack2(float x, float y) {
    unsigned long long r;
    asm("mov.b64 %0, {%1, %2};" : "=l"(r) : "f"(x), "f"(y));
    return r;
}
__device__ __forceinline__ void unpack2(unsigned long long v, float& x, float& y) {
    asm("mov.b64 {%0, %1}, %2;" : "=f"(x), "=f"(y) : "l"(v));
}
__device__ __forceinline__ unsigned long long fma2(unsigned long long a,
                                                   unsigned long long b,
                                                   unsigned long long c) {
    unsigned long long d;
    asm("fma.rn.f32x2 %0, %1, %2, %3;" : "=l"(d) : "l"(a), "l"(b), "l"(c));
    return d;
}

// ---------------- graph preprocessing ----------------
__global__ void zero_cnt_kernel() {
    int i = blockIdx.x * blockDim.x + threadIdx.x;
    if (i < N_NODES) g_cnt[i] = 0;
}

// edge_index is INT32: jnp.int64 silently demotes to int32 (JAX x64 disabled)
__global__ void count_kernel(const int* __restrict__ ei) {
    int e = blockIdx.x * blockDim.x + threadIdx.x;
    if (e < N_EDGES) {
        int dst = ei[N_EDGES + e];
        if (dst >= 0 && dst < N_NODES) atomicAdd(&g_cnt[dst], 1);
    }
}

__global__ void dinv_kernel() {
    int i = blockIdx.x * blockDim.x + threadIdx.x;
    if (i < N_NODES) g_dinv[i] = rsqrtf((float)(g_cnt[i] + 1)); // +1 self-loop
}

// single-block exclusive scan over g_cnt -> g_rowptr (and cursor copy)
__global__ void scan_kernel() {
    __shared__ int sums[1024];
    const int CH = (N_NODES + 1023) / 1024;  // 49
    int t = threadIdx.x;
    int start = t * CH;
    int s = 0;
    for (int i = 0; i < CH; i++) {
        int idx = start + i;
        if (idx < N_NODES) s += g_cnt[idx];
    }
    sums[t] = s;
    __syncthreads();
    for (int off = 1; off < 1024; off <<= 1) {
        int v = 0;
        if (t >= off) v = sums[t - off];
        __syncthreads();
        if (t >= off) sums[t] += v;
        __syncthreads();
    }
    int run = (t == 0) ? 0 : sums[t - 1];
    for (int i = 0; i < CH; i++) {
        int idx = start + i;
        if (idx < N_NODES) {
            g_rowptr[idx] = run;
            g_cursor[idx] = run;
            run += g_cnt[idx];
        }
    }
    if (t == 1023) g_rowptr[N_NODES] = sums[1023];
}

__global__ void fill_kernel(const int* __restrict__ ei) {
    int e = blockIdx.x * blockDim.x + threadIdx.x;
    if (e < N_EDGES) {
        int src = ei[e];
        int dst = ei[N_EDGES + e];
        if (src < 0 || src >= N_NODES || dst < 0 || dst >= N_NODES) return;
        int pos = atomicAdd(&g_cursor[dst], 1);
        g_col[pos] = src;
        g_w[pos]   = g_dinv[src];
    }
}

// ---------------- GEMM1: h1 = X[50000,1433] @ W1[1433,256] ----------------
// 128x64 tile, 256 threads, 8x4 per thread, f32x2-packed accumulation.
#define BM 128
#define BN 64
#define BK 16

__global__ __launch_bounds__(256) void gemm1_kernel(const float* __restrict__ X,
                                                    const float* __restrict__ W1) {
    __shared__ __align__(16) float As[BK][BM + 4];  // row = 132 floats (528B)
    __shared__ __align__(16) float Bs[BK][BN + 4];  // row = 68 floats (272B)

    int t = threadIdx.x;
    int tr = t & 15;   // 16 row groups of 8
    int tc = t >> 4;   // 16 col groups of 4
    int row0 = blockIdx.x * BM;
    int col0 = blockIdx.y * BN;

    // acc2[p][j]: rows (tr*8+2p, tr*8+2p+1), col (tc*4+j), packed f32x2
    unsigned long long acc2[4][4];
#pragma unroll
    for (int p = 0; p < 4; p++)
#pragma unroll
        for (int j = 0; j < 4; j++) acc2[p][j] = 0ull;

    for (int k0 = 0; k0 < F_IN; k0 += BK) {
        // load A tile: 2048 elems, 8 per thread (16 consecutive k per row)
#pragma unroll
        for (int i = 0; i < 8; i++) {
            int idx = t + i * 256;
            int kk = idx & 15;
            int r  = idx >> 4;
            int gr = row0 + r;
            int gk = k0 + kk;
            As[kk][r] = (gr < N_NODES && gk < F_IN) ? X[(size_t)gr * F_IN + gk] : 0.0f;
        }
        // load B tile: 1024 elems, 4 per thread (64 consecutive cols per row)
#pragma unroll
        for (int i = 0; i < 4; i++) {
            int idx = t + i * 256;
            int c  = idx & 63;
            int kk = idx >> 6;
            int gk = k0 + kk;
            Bs[kk][c] = (gk < F_IN) ? W1[gk * HID + col0 + c] : 0.0f;
        }
        __syncthreads();

#pragma unroll
        for (int kk = 0; kk < BK; kk++) {
            const ulonglong2 a01 = *(const ulonglong2*)&As[kk][tr * 8];
            const ulonglong2 a23 = *(const ulonglong2*)&As[kk][tr * 8 + 4];
            unsigned long long ap[4] = {a01.x, a01.y, a23.x, a23.y};
            const float4 bv = *(const float4*)&Bs[kk][tc * 4];
            unsigned long long bb[4] = {pack2(bv.x, bv.x), pack2(bv.y, bv.y),
                                        pack2(bv.z, bv.z), pack2(bv.w, bv.w)};
#pragma unroll
            for (int p = 0; p < 4; p++)
#pragma unroll
                for (int j = 0; j < 4; j++)
                    acc2[p][j] = fma2(ap[p], bb[j], acc2[p][j]);
        }
        __syncthreads();
    }

    // store
#pragma unroll
    for (int p = 0; p < 4; p++) {
        float lo[4], hi[4];
#pragma unroll
        for (int j = 0; j < 4; j++) unpack2(acc2[p][j], lo[j], hi[j]);
        int gr0 = row0 + tr * 8 + 2 * p;
        int gc  = col0 + tc * 4;
        if (gr0 < N_NODES) {
#pragma unroll
            for (int j = 0; j < 4; j++) g_h1[(size_t)gr0 * HID + gc + j] = lo[j];
        }
        if (gr0 + 1 < N_NODES) {
#pragma unroll
            for (int j = 0; j < 4; j++) g_h1[(size_t)(gr0 + 1) * HID + gc + j] = hi[j];
        }
    }
}

// ---------------- Aggregation layer 1: z1 = relu(D^-1/2 A D^-1/2 h1 + b1) ----------------
// one block (64 threads) per dst node; each thread owns 4 contiguous cols (float4)
__global__ __launch_bounds__(64) void agg1_kernel(const float* __restrict__ b1) {
    __shared__ __align__(16) uint2 spair[64];  // {src, bits(w)}
    int u = blockIdx.x;
    int t = threadIdx.x;
    int start = g_rowptr[u];
    int end   = g_rowptr[u + 1];

    float4 acc = make_float4(0.f, 0.f, 0.f, 0.f);
    for (int base = start; base < end; base += 64) {
        int j = base + t;
        if (j < end) {
            spair[t] = make_uint2((unsigned)g_col[j], __float_as_uint(g_w[j]));
        }
        __syncthreads();
        int m = min(64, end - base);
#pragma unroll 4
        for (int q = 0; q < m; q++) {
            uint2 p = spair[q];
            const float4 hv = *(const float4*)&g_h1[(size_t)p.x * HID + t * 4];
            float w = __uint_as_float(p.y);
            acc.x = fmaf(hv.x, w, acc.x);
            acc.y = fmaf(hv.y, w, acc.y);
            acc.z = fmaf(hv.z, w, acc.z);
            acc.w = fmaf(hv.w, w, acc.w);
        }
        __syncthreads();
    }

    float di = g_dinv[u];
    float self = di * di;
    const float4 hs = *(const float4*)&g_h1[(size_t)u * HID + t * 4];
    const float4 bv = *(const float4*)&b1[t * 4];
    float4 o;
    o.x = fmaxf(di * acc.x + self * hs.x + bv.x, 0.f);
    o.y = fmaxf(di * acc.y + self * hs.y + bv.y, 0.f);
    o.z = fmaxf(di * acc.z + self * hs.z + bv.z, 0.f);
    o.w = fmaxf(di * acc.w + self * hs.w + bv.w, 0.f);
    *(float4*)&g_z1[(size_t)u * HID + t * 4] = o;
}

// ---------------- GEMM2: h2 = z1[50000,256] @ W2[256,7] ----------------
// one warp per node; 8 warps / block
__global__ __launch_bounds__(256) void gemm2_kernel(const float* __restrict__ W2) {
    __shared__ float w2s[HID * N_CLS];  // 1792 floats
    int t = threadIdx.x;
    for (int i = t; i < HID * N_CLS; i += 256) w2s[i] = W2[i];
    __syncthreads();

    int warp = t >> 5, lane = t & 31;
    int node = blockIdx.x * 8 + warp;
    if (node >= N_NODES) return;

    float acc[N_CLS];
#pragma unroll
    for (int c = 0; c < N_CLS; c++) acc[c] = 0.f;

#pragma unroll
    for (int kk = 0; kk < 8; kk++) {
        int k = lane + kk * 32;
        float v = g_z1[(size_t)node * HID + k];
#pragma unroll
        for (int c = 0; c < N_CLS; c++) acc[c] = fmaf(v, w2s[k * N_CLS + c], acc[c]);
    }
#pragma unroll
    for (int off = 16; off > 0; off >>= 1) {
#pragma unroll
        for (int c = 0; c < N_CLS; c++)
            acc[c] += __shfl_down_sync(0xffffffffu, acc[c], off);
    }
    if (lane == 0) {
#pragma unroll
        for (int c = 0; c < N_CLS; c++) g_h2[node * N_CLS + c] = acc[c];
    }
}

// ---------------- Aggregation layer 2 -> d_out ----------------
// one warp (block of 32) per dst node; lanes 0..6 own the 7 output cols
__global__ __launch_bounds__(32) void agg2_kernel(const float* __restrict__ b2,
                                                  float* __restrict__ out) {
    __shared__ uint2 spair[32];
    int u = blockIdx.x;
    int t = threadIdx.x;
    int start = g_rowptr[u];
    int end   = g_rowptr[u + 1];

    float acc = 0.f;
    for (int base = start; base < end; base += 32) {
        int j = base + t;
        if (j < end) {
            spair[t] = make_uint2((unsigned)g_col[j], __float_as_uint(g_w[j]));
        }
        __syncwarp();
        int m = min(32, end - base);
        if (t < N_CLS) {
            for (int q = 0; q < m; q++) {
                uint2 p = spair[q];
                acc = fmaf(g_h2[(size_t)p.x * N_CLS + t], __uint_as_float(p.y), acc);
            }
        }
        __syncwarp();
    }
    if (t < N_CLS) {
        float di = g_dinv[u];
        out[u * N_CLS + t] = di * acc + di * di * g_h2[(size_t)u * N_CLS + t] + b2[t];
    }
}

// ---------------- launch ----------------
extern "C" void kernel_launch(void* const* d_in, const int* in_sizes, int n_in,
                              void* d_out, int out_size) {
    const float* x   = (const float*)d_in[0];
    const int*   ei  = (const int*)d_in[1];   // int32! (JAX x64 disabled)
    const float* W1  = (const float*)d_in[2];
    const float* b1  = (const float*)d_in[3];
    const float* W2  = (const float*)d_in[4];
    const float* b2  = (const float*)d_in[5];
    float* out = (float*)d_out;

    // graph preprocessing (shared by both layers)
    zero_cnt_kernel<<<(N_NODES + 255) / 256, 256>>>();
    count_kernel<<<(N_EDGES + 255) / 256, 256>>>(ei);
    dinv_kernel<<<(N_NODES + 255) / 256, 256>>>();
    scan_kernel<<<1, 1024>>>();
    fill_kernel<<<(N_EDGES + 255) / 256, 256>>>(ei);

    // layer 1
    dim3 g1((N_NODES + BM - 1) / BM, HID / BN);
    gemm1_kernel<<<g1, 256>>>(x, W1);
    agg1_kernel<<<N_NODES, 64>>>(b1);

    // layer 2
    gemm2_kernel<<<(N_NODES + 7) / 8, 256>>>(W2);
    agg2_kernel<<<N_NODES, 32>>>(b2, out);
}